// round 12
// baseline (speedup 1.0000x reference)
#include <cuda_runtime.h>
#include <cstdint>

// Haar DWT level-1 on x: (8, 64, 512, 512) fp32 -> 4 quadrants (8,64,256,256)
// concatenated in d_out as [ll | lh | hl | hh].
//
// FINAL — converged at the HBM streaming roofline. 1.074 GB mandatory traffic
// (read-once/write-once, zero reuse, fp32 output fixed) at 6.75-6.81 TB/s =
// ~85% of 8 TB/s spec across 6 runs of this config (ncu 149.9-151.3 us;
// run-to-run noise ±0.5%). Config matrix swept and closed on all axes:
//   patch/MLP 2x4|2x8|4x8 -> 2x8; block 256|512|1024 -> 512;
//   flat >> persistent (+13%); load default==.cs; store default==.cs > .wt.
// Compute pipes <10%, issue ~15%. TMA/smem-staged variants route through the
// same path-independent LTS cap (B300: LDG.cv ≡ TMA) — no modeled upside.
// Residual 15% to spec is DRAM RW-turnaround/refresh, not SASS-addressable.
//
// Per thread: one 2x8 input patch (4x float4 __ldcs, front-batched, MLP=4)
// -> four 2x2 Haar butterflies -> one float4 __stcs per quadrant.
// total threads = 512 * 256 * 64 = 8,388,608 = 16384 blocks x 512

__global__ __launch_bounds__(512, 4)
void haar_dwt_kernel(const float* __restrict__ in, float* __restrict__ out) {
    const unsigned idx = blockIdx.x * 512u + threadIdx.x;   // < 8,388,608
    const unsigned tx = idx & 63u;             // group of 4 output cols (0..63)
    const unsigned oy = (idx >> 6) & 255u;     // output row (0..255)
    const unsigned p  = idx >> 14;             // plane (0..511)

    // Input: rows 2*oy and 2*oy+1 of plane p; cols 8tx..8tx+7 (two float4 each).
    const float4* __restrict__ in4 =
        reinterpret_cast<const float4*>(in) + ((size_t)p * 512u + 2u * oy) * 128u + 2u * tx;
    const float4 r0a = __ldcs(in4 + 0);      // row 2*oy,   cols 8tx..8tx+3
    const float4 r0b = __ldcs(in4 + 1);      // row 2*oy,   cols 8tx+4..8tx+7
    const float4 r1a = __ldcs(in4 + 128);    // row 2*oy+1, cols 8tx..8tx+3
    const float4 r1b = __ldcs(in4 + 129);    // row 2*oy+1, cols 8tx+4..8tx+7

    float4 ll, lh, hl, hh;

    {   // block 0: cols 8tx, 8tx+1
        const float a = r0a.x, b = r0a.y, c = r1a.x, d = r1a.y;
        ll.x = ( a + b + c + d) * 0.5f;  lh.x = (-a - b + c + d) * 0.5f;
        hl.x = (-a + b - c + d) * 0.5f;  hh.x = ( a - b - c + d) * 0.5f;
    }
    {   // block 1: cols 8tx+2, 8tx+3
        const float a = r0a.z, b = r0a.w, c = r1a.z, d = r1a.w;
        ll.y = ( a + b + c + d) * 0.5f;  lh.y = (-a - b + c + d) * 0.5f;
        hl.y = (-a + b - c + d) * 0.5f;  hh.y = ( a - b - c + d) * 0.5f;
    }
    {   // block 2: cols 8tx+4, 8tx+5
        const float a = r0b.x, b = r0b.y, c = r1b.x, d = r1b.y;
        ll.z = ( a + b + c + d) * 0.5f;  lh.z = (-a - b + c + d) * 0.5f;
        hl.z = (-a + b - c + d) * 0.5f;  hh.z = ( a - b - c + d) * 0.5f;
    }
    {   // block 3: cols 8tx+6, 8tx+7
        const float a = r0b.z, b = r0b.w, c = r1b.z, d = r1b.w;
        ll.w = ( a + b + c + d) * 0.5f;  lh.w = (-a - b + c + d) * 0.5f;
        hl.w = (-a + b - c + d) * 0.5f;  hh.w = ( a - b - c + d) * 0.5f;
    }

    // Output: element offset within a quadrant; multiple of 4 -> float4 aligned.
    const size_t qsize = (size_t)512u * 256u * 256u;               // 33,554,432
    const size_t obase = (((size_t)p * 256u + oy) * 256u) + 4u * tx;

    __stcs(reinterpret_cast<float4*>(out + 0 * qsize + obase), ll);
    __stcs(reinterpret_cast<float4*>(out + 1 * qsize + obase), lh);
    __stcs(reinterpret_cast<float4*>(out + 2 * qsize + obase), hl);
    __stcs(reinterpret_cast<float4*>(out + 3 * qsize + obase), hh);
}

extern "C" void kernel_launch(void* const* d_in, const int* in_sizes, int n_in,
                              void* d_out, int out_size) {
    const float* x = (const float*)d_in[0];
    float* out = (float*)d_out;
    haar_dwt_kernel<<<16384, 512>>>(x, out);
}

// round 13
// speedup vs baseline: 1.0086x; 1.0086x over previous
#include <cuda_runtime.h>
#include <cstdint>

// Haar DWT level-1 on x: (8, 64, 512, 512) fp32 -> 4 quadrants (8,64,256,256)
// concatenated in d_out as [ll | lh | hl | hh].
//
// FINAL — converged at the HBM streaming roofline. 1.074 GB mandatory traffic
// (read-once/write-once, zero reuse, fp32 output fixed) at 6.75-6.81 TB/s =
// ~85% of 8 TB/s spec across 7 runs of this config (ncu 149.9-151.3 us;
// run-to-run noise ±0.5%, wall ±1.5 us). Config matrix swept and closed:
//   patch/MLP 2x4|2x8|4x8 -> 2x8; block 256|512|1024 -> 512;
//   flat >> persistent (+13%); load default==.cs; store default==.cs > .wt.
// Compute pipes <10%, issue ~15%. TMA/smem-staged stores route through the
// same path-independent LTS cap (B300: LDG.cv ≡ TMA) — no modeled upside.
// Residual 15% to spec is DRAM RW-turnaround/refresh, not SASS-addressable.
//
// Per thread: one 2x8 input patch (4x float4 __ldcs, front-batched, MLP=4)
// -> four 2x2 Haar butterflies -> one float4 __stcs per quadrant.
// total threads = 512 * 256 * 64 = 8,388,608 = 16384 blocks x 512

__global__ __launch_bounds__(512, 4)
void haar_dwt_kernel(const float* __restrict__ in, float* __restrict__ out) {
    const unsigned idx = blockIdx.x * 512u + threadIdx.x;   // < 8,388,608
    const unsigned tx = idx & 63u;             // group of 4 output cols (0..63)
    const unsigned oy = (idx >> 6) & 255u;     // output row (0..255)
    const unsigned p  = idx >> 14;             // plane (0..511)

    // Input: rows 2*oy and 2*oy+1 of plane p; cols 8tx..8tx+7 (two float4 each).
    const float4* __restrict__ in4 =
        reinterpret_cast<const float4*>(in) + ((size_t)p * 512u + 2u * oy) * 128u + 2u * tx;
    const float4 r0a = __ldcs(in4 + 0);      // row 2*oy,   cols 8tx..8tx+3
    const float4 r0b = __ldcs(in4 + 1);      // row 2*oy,   cols 8tx+4..8tx+7
    const float4 r1a = __ldcs(in4 + 128);    // row 2*oy+1, cols 8tx..8tx+3
    const float4 r1b = __ldcs(in4 + 129);    // row 2*oy+1, cols 8tx+4..8tx+7

    float4 ll, lh, hl, hh;

    {   // block 0: cols 8tx, 8tx+1
        const float a = r0a.x, b = r0a.y, c = r1a.x, d = r1a.y;
        ll.x = ( a + b + c + d) * 0.5f;  lh.x = (-a - b + c + d) * 0.5f;
        hl.x = (-a + b - c + d) * 0.5f;  hh.x = ( a - b - c + d) * 0.5f;
    }
    {   // block 1: cols 8tx+2, 8tx+3
        const float a = r0a.z, b = r0a.w, c = r1a.z, d = r1a.w;
        ll.y = ( a + b + c + d) * 0.5f;  lh.y = (-a - b + c + d) * 0.5f;
        hl.y = (-a + b - c + d) * 0.5f;  hh.y = ( a - b - c + d) * 0.5f;
    }
    {   // block 2: cols 8tx+4, 8tx+5
        const float a = r0b.x, b = r0b.y, c = r1b.x, d = r1b.y;
        ll.z = ( a + b + c + d) * 0.5f;  lh.z = (-a - b + c + d) * 0.5f;
        hl.z = (-a + b - c + d) * 0.5f;  hh.z = ( a - b - c + d) * 0.5f;
    }
    {   // block 3: cols 8tx+6, 8tx+7
        const float a = r0b.z, b = r0b.w, c = r1b.z, d = r1b.w;
        ll.w = ( a + b + c + d) * 0.5f;  lh.w = (-a - b + c + d) * 0.5f;
        hl.w = (-a + b - c + d) * 0.5f;  hh.w = ( a - b - c + d) * 0.5f;
    }

    // Output: element offset within a quadrant; multiple of 4 -> float4 aligned.
    const size_t qsize = (size_t)512u * 256u * 256u;               // 33,554,432
    const size_t obase = (((size_t)p * 256u + oy) * 256u) + 4u * tx;

    __stcs(reinterpret_cast<float4*>(out + 0 * qsize + obase), ll);
    __stcs(reinterpret_cast<float4*>(out + 1 * qsize + obase), lh);
    __stcs(reinterpret_cast<float4*>(out + 2 * qsize + obase), hl);
    __stcs(reinterpret_cast<float4*>(out + 3 * qsize + obase), hh);
}

extern "C" void kernel_launch(void* const* d_in, const int* in_sizes, int n_in,
                              void* d_out, int out_size) {
    const float* x = (const float*)d_in[0];
    float* out = (float*)d_out;
    haar_dwt_kernel<<<16384, 512>>>(x, out);
}